// round 11
// baseline (speedup 1.0000x reference)
#include <cuda_runtime.h>
#include <math.h>

#define NB   32      // batch
#define NC   512     // channels
#define HW   4096    // 64*64
#define NSEG 129     // segment ids 0..128 (0 dropped later)
#define NSG  128     // kept segments
#define NCLS 19
#define ATTH 512
#define MTOT (NB * NSG)   // 4096 GEMM rows
#define NTILE 32          // 128-pixel tiles per batch

typedef unsigned long long u64;

#define FMA_F32X2(d, a, b, c) \
    asm("fma.rn.f32x2 %0, %1, %2, %3;" : "=l"(d) : "l"(a), "l"(b), "l"(c))
#define PACK_DUP_F32X2(d, s) \
    asm("mov.b64 %0, {%1, %1};" : "=l"(d) : "r"(__float_as_uint(s)))
#define UNPACK_F32X2(lo, hi, in) \
    asm("mov.b64 {%0, %1}, %2;" : "=r"(lo), "=r"(hi) : "l"(in))

// ---- scratch (device globals; no allocation allowed) ----
__device__ int   g_cnt[NB * NSEG];
__device__ float g_invc[NB * NSEG];
__device__ int   g_sorted[NB * HW];          // per tile: 128 packed ((id*33)<<16 | pos*33)
__device__ int   g_toff[NB * NTILE * 16];    // per tile: 16 warp start offsets
__device__ float g_meansT[NC * MTOT];        // [c][m]: GEMM A (m-contig) + wm reads
__device__ float g_att[MTOT];

// ============================================================
// Kernel 0: zero counters / att accumulator, init out = bh.
// ============================================================
__global__ void zero_kernel(const float* __restrict__ bh,
                            float* __restrict__ out) {
    int t = blockIdx.x * 256 + threadIdx.x;   // grid 17 -> 4352
    if (t < MTOT) g_att[t] = 0.0f;
    if (t < NB * NSEG) g_cnt[t] = 0;
    if (t < NB * NCLS) out[t] = bh[t % NCLS];
}

// ============================================================
// Kernel 1: downsample + per-tile counting sort of segment ids.
// Emits packed sorted entries ((id*33)<<16 | pos*33) plus 16
// per-warp start offsets (seg warp w owns ids [8w, 8w+8); warp
// 15 takes id 128 too). Accumulates global per-(b,id) counts.
// ============================================================
__global__ void prep_sort_kernel(const int* __restrict__ mask) {
    int b = blockIdx.y, tile = blockIdx.x;
    int t = threadIdx.x;
    __shared__ int hist[NSEG];
    __shared__ int pref[NSEG];
    __shared__ int sid[128];

    for (int i = t; i < NSEG; i += 128) hist[i] = 0;
    __syncthreads();

    int p = tile * 128 + t;
    int i = p >> 6, j = p & 63;
    int id = mask[((long long)b * 512 + i * 8) * 512 + j * 8];
    id = min(max(id, 0), NSEG - 1);
    sid[t] = id;
    atomicAdd(&hist[id], 1);
    __syncthreads();

    if (t == 0) {
        int s = 0;
        for (int k = 0; k < NSEG; ++k) { pref[k] = s; s += hist[k]; }
    }
    __syncthreads();

    for (int k = t; k < NSEG; k += 128)
        if (hist[k]) atomicAdd(&g_cnt[b * NSEG + k], hist[k]);
    if (t < 16) g_toff[(b * NTILE + tile) * 16 + t] = pref[t * 8];
    __syncthreads();   // toff reads done before pref is mutated

    int rank = atomicAdd(&pref[sid[t]], 1);
    g_sorted[(b * NTILE + tile) * 128 + rank] = ((sid[t] * 33) << 16) | (t * 33);
}

// ============================================================
// Kernel 2 (tiny): counts -> inverse counts.
// ============================================================
__global__ void invc_kernel() {
    int t = threadIdx.x;   // 160 threads, grid NB
    int b = blockIdx.x;
    if (t < NSEG) {
        int cv = g_cnt[b * NSEG + t];
        g_invc[b * NSEG + t] = (t >= 1 && cv > 0) ? (1.0f / (float)cv) : 0.0f;
    }
}

// ============================================================
// Kernel 3: segment sums, sorted branchless scatter, 512 thr /
// 16 warps (warp w owns ids [8w, 8w+8); warp 15 takes 128).
// 48 warps/SM (vs 27.7 at 256 thr) to cover the LDS->FADD->STS
// RMW chain latency. One shared accumulator, no atomics.
// ============================================================
#define SEG_SMEM ((128 * 33 + NSEG * 33) * 4)

__global__ void __launch_bounds__(512, 3)
seg_kernel(const float* __restrict__ x) {
    extern __shared__ float sseg[];
    float* s_tile = sseg;               // [128 pos][33] (col = channel)
    float* s_acc  = sseg + 128 * 33;    // [129 id][33]
    __shared__ int s_sorted[128];
    __shared__ int s_off[16];
    __shared__ float s_invc[NSEG];

    int b = blockIdx.y;
    int cbase = blockIdx.x * 32;
    int tid = threadIdx.x;
    int w = tid >> 5, lane = tid & 31;

    for (int t = tid; t < NSEG * 33; t += 512) s_acc[t] = 0.0f;
    for (int t = tid; t < NSEG; t += 512) s_invc[t] = g_invc[b * NSEG + t];

    int cf = tid >> 4, qf = tid & 15;   // staging: channel cf, f4-slot qf(+16k)
    const float4* xp = (const float4*)x + (long long)(b * NC + cbase + cf) * (HW / 4);
    const int* sortb = g_sorted + (long long)b * HW;
    const int* toffb = g_toff + b * NTILE * 16;

    // prefetch tile 0
    float4 pf[2];
    int rsort = 0, roff = 0;
    #pragma unroll
    for (int k = 0; k < 2; ++k) pf[k] = xp[qf + 16 * k];
    if (tid < 128) rsort = sortb[tid];
    if (tid < 16)  roff  = toffb[tid];

    #pragma unroll 1
    for (int tile = 0; tile < NTILE; ++tile) {
        __syncthreads();   // scatter of tile-1 done; acc-zero on 1st
        // commit staged tile (conflict-free scalar STS)
        #pragma unroll
        for (int k = 0; k < 2; ++k) {
            int f4 = qf + 16 * k;
            float* o = s_tile + (f4 * 4) * 33 + cf;
            o[0] = pf[k].x; o[33] = pf[k].y; o[66] = pf[k].z; o[99] = pf[k].w;
        }
        if (tid < 128) s_sorted[tid] = rsort;
        if (tid < 16)  s_off[tid]    = roff;
        __syncthreads();   // staging visible

        // prefetch next tile (overlaps the scatter below)
        if (tile + 1 < NTILE) {
            #pragma unroll
            for (int k = 0; k < 2; ++k) pf[k] = xp[(tile + 1) * 32 + qf + 16 * k];
            if (tid < 128) rsort = sortb[(tile + 1) * 128 + tid];
            if (tid < 16)  roff  = toffb[(tile + 1) * 16 + tid];
        }

        // branchless scatter (s>>16 = id*33, s&0xffff = pos*33)
        int e   = s_off[w];
        int end = (w == 15) ? 128 : s_off[w + 1];
        #pragma unroll 4
        for (; e < end; ++e) {
            int s = s_sorted[e];
            s_acc[(s >> 16) + lane] += s_tile[(s & 0xffff) + lane];
        }
    }
    __syncthreads();

    // write meansT [c][m] (coalesced over segment)
    for (int t = tid; t < NSG * 32; t += 512) {
        int sm1 = t & 127, c = t >> 7;
        g_meansT[(long long)(cbase + c) * MTOT + b * NSG + sm1] =
            s_acc[(sm1 + 1) * 33 + c] * s_invc[sm1 + 1];
    }
}

// ============================================================
// Kernel 4: att logits GEMM. hidden = relu(meansT' @ Wa1 + ba1);
// g_att[m] += hidden_tile @ Wa2 (hidden never stored).
// BM=128, BN=64, BK=32, double-buffered, 256 thr, 8m x 4n f32x2.
// ============================================================
#define GBM 128
#define GBN 64
#define GBK 32
#define ASTR 136
#define GEMM_SMEM ((2 * GBK * ASTR + 2 * GBK * GBN) * 4)

__global__ void __launch_bounds__(256, 2)
att_gemm_kernel(const float* __restrict__ Wa1,
                const float* __restrict__ ba1,
                const float* __restrict__ Wa2) {
    extern __shared__ float sm[];
    float* AstBuf = sm;
    float* BsBuf  = sm + 2 * GBK * ASTR;

    int tid = threadIdx.x;
    int mbase = blockIdx.y * GBM;
    int nbase = blockIdx.x * GBN;
    int tx = tid & 15, ty = tid >> 4;

    int am = tid & 31, akr = tid >> 5;
    int br = tid >> 4, bc = (tid & 15) * 4;
    const float* Ag = g_meansT + (long long)akr * MTOT + mbase + am * 4;
    const float* Bg = Wa1 + (long long)br * ATTH + nbase + bc;

    u64 acc2[4][4];
    #pragma unroll
    for (int i = 0; i < 4; ++i)
        #pragma unroll
        for (int j = 0; j < 4; ++j) acc2[i][j] = 0ULL;

    float4 pa[4], pb[2];
    #pragma unroll
    for (int p = 0; p < 4; ++p) pa[p] = *(const float4*)(Ag + (long long)(8 * p) * MTOT);
    #pragma unroll
    for (int p = 0; p < 2; ++p) pb[p] = *(const float4*)(Bg + (long long)(16 * p) * ATTH);

    const int NITER = NC / GBK;
    int cur = 0;
    #pragma unroll 1
    for (int it = 0; it < NITER; ++it) {
        float* Ac = AstBuf + cur * GBK * ASTR;
        float* Bc = BsBuf + cur * GBK * GBN;
        #pragma unroll
        for (int p = 0; p < 4; ++p)
            *(float4*)(Ac + (akr + 8 * p) * ASTR + am * 4) = pa[p];
        #pragma unroll
        for (int p = 0; p < 2; ++p)
            *(float4*)(Bc + (br + 16 * p) * GBN + bc) = pb[p];
        __syncthreads();

        if (it + 1 < NITER) {
            long long k0n = (long long)(it + 1) * GBK;
            #pragma unroll
            for (int p = 0; p < 4; ++p)
                pa[p] = *(const float4*)(Ag + (k0n + 8 * p) * MTOT);
            #pragma unroll
            for (int p = 0; p < 2; ++p)
                pb[p] = *(const float4*)(Bg + (k0n + 16 * p) * ATTH);
        }

        #pragma unroll
        for (int kk = 0; kk < GBK; ++kk) {
            const float* Ak = Ac + kk * ASTR + ty * 8;
            ulonglong2 a01 = *(const ulonglong2*)(Ak);
            ulonglong2 a23 = *(const ulonglong2*)(Ak + 4);
            float4 b4 = *(const float4*)(Bc + kk * GBN + tx * 4);
            u64 a2[4] = { a01.x, a01.y, a23.x, a23.y };
            u64 bd[4];
            PACK_DUP_F32X2(bd[0], b4.x);
            PACK_DUP_F32X2(bd[1], b4.y);
            PACK_DUP_F32X2(bd[2], b4.z);
            PACK_DUP_F32X2(bd[3], b4.w);
            #pragma unroll
            for (int mp = 0; mp < 4; ++mp) {
                FMA_F32X2(acc2[mp][0], a2[mp], bd[0], acc2[mp][0]);
                FMA_F32X2(acc2[mp][1], a2[mp], bd[1], acc2[mp][1]);
                FMA_F32X2(acc2[mp][2], a2[mp], bd[2], acc2[mp][2]);
                FMA_F32X2(acc2[mp][3], a2[mp], bd[3], acc2[mp][3]);
            }
        }
        cur ^= 1;
    }

    float b1[4], w2[4];
    #pragma unroll
    for (int j = 0; j < 4; ++j) {
        int n = nbase + tx * 4 + j;
        b1[j] = ba1[n];
        w2[j] = Wa2[n];
    }
    #pragma unroll
    for (int mp = 0; mp < 4; ++mp) {
        float p0 = 0.0f, p1 = 0.0f;
        #pragma unroll
        for (int j = 0; j < 4; ++j) {
            unsigned lo, hi;
            UNPACK_F32X2(lo, hi, acc2[mp][j]);
            float h0 = fmaxf(__uint_as_float(lo) + b1[j], 0.0f);
            float h1 = fmaxf(__uint_as_float(hi) + b1[j], 0.0f);
            p0 += h0 * w2[j];
            p1 += h1 * w2[j];
        }
        #pragma unroll
        for (int o = 8; o > 0; o >>= 1) {
            p0 += __shfl_xor_sync(0xffffffffu, p0, o);
            p1 += __shfl_xor_sync(0xffffffffu, p1, o);
        }
        if (tx == 0) {
            atomicAdd(&g_att[mbase + ty * 8 + 2 * mp + 0], p0);
            atomicAdd(&g_att[mbase + ty * 8 + 2 * mp + 1], p1);
        }
    }
}

// ============================================================
// Kernel 5: fused softmax + weighted mean + partial class dots.
// Reads meansT [c][m]: segment loop is contiguous per thread.
// ============================================================
__global__ void wm_kernel(const float* __restrict__ Wh,
                          const float* __restrict__ ba2,
                          float* __restrict__ out) {
    int b = blockIdx.y, cg = blockIdx.x, t = threadIdx.x;
    int lane = t & 31, w = t >> 5;
    __shared__ float satt[NSG];
    __shared__ float red[4];

    float v = g_att[b * NSG + t] + ba2[0];
    float m = v;
    #pragma unroll
    for (int o = 16; o > 0; o >>= 1) m = fmaxf(m, __shfl_xor_sync(0xffffffffu, m, o));
    if (lane == 0) red[w] = m;
    __syncthreads();
    m = fmaxf(fmaxf(red[0], red[1]), fmaxf(red[2], red[3]));
    float e = expf(v - m);
    float s = e;
    #pragma unroll
    for (int o = 16; o > 0; o >>= 1) s += __shfl_xor_sync(0xffffffffu, s, o);
    __syncthreads();
    if (lane == 0) red[w] = s;
    __syncthreads();
    s = red[0] + red[1] + red[2] + red[3];
    satt[t] = e / s;
    __syncthreads();

    int c = cg * 128 + t;
    float wm = 0.0f;
    const float* mp = g_meansT + (long long)c * MTOT + b * NSG;
    #pragma unroll 8
    for (int sg = 0; sg < NSG; ++sg) wm += satt[sg] * mp[sg];

    const float* whr = Wh + (long long)c * NCLS;
    #pragma unroll 1
    for (int cls = 0; cls < NCLS; ++cls) {
        float p = wm * whr[cls];
        #pragma unroll
        for (int o = 16; o > 0; o >>= 1) p += __shfl_xor_sync(0xffffffffu, p, o);
        if (lane == 0) atomicAdd(&out[b * NCLS + cls], p);
    }
}

// ============================================================
// Kernel 6: BCE-with-logits loss, mean over all 608 elements.
// ============================================================
__global__ void loss_kernel(const float* __restrict__ target,
                            float* __restrict__ out, int out_size) {
    const int n = NB * NCLS;   // 608
    int t = threadIdx.x;
    float v = 0.0f;
    if (t < n) {
        float l = out[t];
        float tg = target[t];
        v = fmaxf(l, 0.0f) - l * tg + log1pf(expf(-fabsf(l)));
    }
    __shared__ float red[32];
    int lane = t & 31, warp = t >> 5;
    #pragma unroll
    for (int o = 16; o > 0; o >>= 1) v += __shfl_xor_sync(0xffffffffu, v, o);
    if (lane == 0) red[warp] = v;
    __syncthreads();
    if (t < 32) {
        float s = (t < 20) ? red[t] : 0.0f;
        #pragma unroll
        for (int o = 16; o > 0; o >>= 1) s += __shfl_xor_sync(0xffffffffu, s, o);
        if (t == 0) out[out_size - 1] = s / (float)n;
    }
}

// ============================================================
extern "C" void kernel_launch(void* const* d_in, const int* in_sizes, int n_in,
                              void* d_out, int out_size) {
    const float* x      = (const float*)d_in[0];
    const int*   mask   = (const int*)d_in[1];
    const float* target = (const float*)d_in[2];
    const float* Wa1    = (const float*)d_in[3];
    const float* ba1    = (const float*)d_in[4];
    const float* Wa2    = (const float*)d_in[5];
    const float* ba2    = (const float*)d_in[6];
    const float* Wh     = (const float*)d_in[7];
    const float* bh     = (const float*)d_in[8];
    float* out = (float*)d_out;

    cudaFuncSetAttribute(seg_kernel,
                         cudaFuncAttributeMaxDynamicSharedMemorySize, SEG_SMEM);
    cudaFuncSetAttribute(att_gemm_kernel,
                         cudaFuncAttributeMaxDynamicSharedMemorySize, GEMM_SMEM);

    zero_kernel<<<17, 256>>>(bh, out);                                   // idx 0
    prep_sort_kernel<<<dim3(NTILE, NB), 128>>>(mask);                    // idx 1
    invc_kernel<<<NB, 160>>>();                                          // idx 2
    seg_kernel<<<dim3(16, NB), 512, SEG_SMEM>>>(x);                      // idx 3 (profiled)
    att_gemm_kernel<<<dim3(ATTH / GBN, MTOT / GBM), 256, GEMM_SMEM>>>(Wa1, ba1, Wa2); // idx 4
    wm_kernel<<<dim3(4, NB), 128>>>(Wh, ba2, out);                       // idx 5
    loss_kernel<<<1, 640>>>(target, out, out_size);                      // idx 6
}